// round 15
// baseline (speedup 1.0000x reference)
#include <cuda_runtime.h>
#include <cuda_bf16.h>
#include <math.h>
#include <stdint.h>

#define BATCH   4
#define SEQ     4096
#define DMODEL  1024
#define DINNER  2048
#define DSTATE  16
#define DTRANK  64
#define NTOK    (BATCH * SEQ)          // 16384
#define DBL_W   (DTRANK + 2 * DSTATE)  // 96

typedef __nv_bfloat16 bf16;
typedef __nv_bfloat162 bf162;

// ---------------- scratch (static device globals: allocation-free) ----------
__device__ bf16  g_xz [(size_t)NTOK * 2 * DINNER];   // bf16: conv input + z gate
__device__ float g_dt [(size_t)NTOK * DINNER];       // fp32: exp-sensitive
__device__ bf16  g_u  [(size_t)NTOK * DMODEL];
__device__ bf16  g_xc [(size_t)NTOK * DINNER];
__device__ bf16  g_dbl[(size_t)NTOK * DBL_W];
__device__ bf16  g_y  [(size_t)NTOK * DINNER];
#define W_IN_SZ  ((size_t)(2 * DINNER) * DMODEL)
#define W_X_SZ   ((size_t)DBL_W * DINNER)
#define W_DT_SZ  ((size_t)DINNER * DTRANK)
#define W_OUT_SZ ((size_t)DMODEL * DINNER)
__device__ bf16 g_w_in [W_IN_SZ];
__device__ bf16 g_w_x  [W_X_SZ];
__device__ bf16 g_w_dt [W_DT_SZ];
__device__ bf16 g_w_out[W_OUT_SZ];

// ---------------- helpers ----------------------------------------------------
__device__ __forceinline__ uint32_t cvta_smem_u32(const void* p) {
    uint32_t a;
    asm("{ .reg .u64 t; cvta.to.shared.u64 t, %1; cvt.u32.u64 %0, t; }"
        : "=r"(a) : "l"(p));
    return a;
}
__device__ __forceinline__ void cp16(uint32_t sdst, const void* gsrc, bool valid) {
    int sz = valid ? 16 : 0;
    asm volatile("cp.async.cg.shared.global [%0], [%1], 16, %2;"
                 :: "r"(sdst), "l"(gsrc), "r"(sz) : "memory");
}
#define CP_COMMIT() asm volatile("cp.async.commit_group;" ::: "memory")
#define CP_WAIT(n)  asm volatile("cp.async.wait_group %0;" :: "n"(n) : "memory")

__device__ __forceinline__ void mma_bf16(float* d, const uint32_t* a,
                                         const uint32_t* b) {
    asm volatile(
        "mma.sync.aligned.m16n8k16.row.col.f32.bf16.bf16.f32 "
        "{%0,%1,%2,%3}, {%4,%5,%6,%7}, {%8,%9}, {%0,%1,%2,%3};"
        : "+f"(d[0]), "+f"(d[1]), "+f"(d[2]), "+f"(d[3])
        : "r"(a[0]), "r"(a[1]), "r"(a[2]), "r"(a[3]), "r"(b[0]), "r"(b[1]));
}

__device__ __forceinline__ void store_pair(float* C, size_t off, float v0, float v1) {
    float2 o; o.x = v0; o.y = v1;
    *reinterpret_cast<float2*>(C + off) = o;
}
__device__ __forceinline__ void store_pair(bf16* C, size_t off, float v0, float v1) {
    *reinterpret_cast<bf162*>(C + off) = __floats2bfloat162_rn(v0, v1);
}

// ---------------- weight f32 -> bf16 pre-pass (all 4, 1 kernel) -------------
__global__ __launch_bounds__(256) void cvt_weights_kernel(
    const float4* __restrict__ w_in_s,  bf16* __restrict__ w_in_d,
    const float4* __restrict__ w_x_s,   bf16* __restrict__ w_x_d,
    const float4* __restrict__ w_dt_s,  bf16* __restrict__ w_dt_d,
    const float4* __restrict__ w_out_s, bf16* __restrict__ w_out_d)
{
    const int n0 = W_IN_SZ / 4, n1 = n0 + W_X_SZ / 4;
    const int n2 = n1 + W_DT_SZ / 4, n3 = n2 + W_OUT_SZ / 4;
    int i = blockIdx.x * 256 + threadIdx.x;
    const float4* src; bf16* dst; int off;
    if      (i < n0) { src = w_in_s;  dst = w_in_d;  off = i; }
    else if (i < n1) { src = w_x_s;   dst = w_x_d;   off = i - n0; }
    else if (i < n2) { src = w_dt_s;  dst = w_dt_d;  off = i - n1; }
    else if (i < n3) { src = w_out_s; dst = w_out_d; off = i - n2; }
    else return;
    float4 v = src[off];
    bf162 lo = __floats2bfloat162_rn(v.x, v.y);
    bf162 hi = __floats2bfloat162_rn(v.z, v.w);
    uint2 o;
    o.x = *reinterpret_cast<uint32_t*>(&lo);
    o.y = *reinterpret_cast<uint32_t*>(&hi);
    *reinterpret_cast<uint2*>(dst + (size_t)off * 4) = o;
}

// ================ bf16 mma.sync GEMM: C = A[M,K] @ W[N,K]^T =================
// CTA 128x256, 256 threads (8 warps 2x4), warp tile 64x64 (4x8 m16n8k16).
// BK=32 bf16 per stage, 4-stage cp.async, scalar-LDS fragment loads, 1 CTA/SM.
// EPI: 0 none, 1 softplus(acc+bias[n]), 2 acc+resid. OutT: float or bf16.

#define SSTRIDE 20               // 4B words per 32-bf16 row (16 data + 4 pad)
#define AS_W    (128 * SSTRIDE)
#define BS_W    (256 * SSTRIDE)
#define STAGE_W (AS_W + BS_W)    // 7680 words = 30720 B
#define NSTAGE  4
#define GEMM_SMEM_BYTES (NSTAGE * STAGE_W * 4)   // 122880

template <int EPI, typename OutT>
__global__ __launch_bounds__(256, 1) void mma_gemm_kernel(
    const bf16* __restrict__ A, int lda,
    const bf16* __restrict__ W, int ldb,
    OutT* __restrict__ C, int ldc,
    int N, int K,
    const float* __restrict__ bias,
    const float* __restrict__ resid)
{
    extern __shared__ uint32_t sm[];
    uint32_t smb = cvta_smem_u32(sm);

    int tid = threadIdx.x;
    int lane = tid & 31;
    int q = lane >> 2, c = lane & 3;
    int wid = tid >> 5;
    int wm = wid >> 2, wn = wid & 3;            // 2 x 4 warp grid
    int brow = blockIdx.y * 128, bcol = blockIdx.x * 256;

    // cp.async mapping: rows tid>>2 (+64k), 16B piece tid&3; row = 64B of bf16
    int rA = tid >> 2;                          // 0..63
    int pq = (tid & 3) * 16;                    // byte piece within row
    const char* gA0 = (const char*)(A + (size_t)(brow + rA) * lda) + pq;
    const char* gA1 = (const char*)(A + (size_t)(brow + rA + 64) * lda) + pq;
    bool bv0 = (bcol + rA)       < N;
    bool bv1 = (bcol + rA + 64)  < N;
    bool bv2 = (bcol + rA + 128) < N;
    bool bv3 = (bcol + rA + 192) < N;
    const char* gB0 = (const char*)(W + (size_t)(bv0 ? bcol + rA       : 0) * ldb) + pq;
    const char* gB1 = (const char*)(W + (size_t)(bv1 ? bcol + rA + 64  : 0) * ldb) + pq;
    const char* gB2 = (const char*)(W + (size_t)(bv2 ? bcol + rA + 128 : 0) * ldb) + pq;
    const char* gB3 = (const char*)(W + (size_t)(bv3 ? bcol + rA + 192 : 0) * ldb) + pq;

    uint32_t sA0 = smb + (uint32_t)(rA * SSTRIDE) * 4 + pq;
    uint32_t sA1 = sA0 + 64 * SSTRIDE * 4;
    uint32_t sB0 = smb + (uint32_t)(AS_W + rA * SSTRIDE) * 4 + pq;
    uint32_t sB1 = sB0 + 64  * SSTRIDE * 4;
    uint32_t sB2 = sB0 + 128 * SSTRIDE * 4;
    uint32_t sB3 = sB0 + 192 * SSTRIDE * 4;

    int nch = K >> 5;                  // BK = 32 bf16 (64 bytes per row)
    int npro = nch < 3 ? nch : 3;

    for (int p = 0; p < npro; p++) {
        uint32_t so = (uint32_t)p * (STAGE_W * 4);
        size_t ko = (size_t)(p << 5) * 2;       // 32 bf16 = 64 bytes
        cp16(sA0 + so, gA0 + ko, true);
        cp16(sA1 + so, gA1 + ko, true);
        cp16(sB0 + so, gB0 + ko, bv0);
        cp16(sB1 + so, gB1 + ko, bv1);
        cp16(sB2 + so, gB2 + ko, bv2);
        cp16(sB3 + so, gB3 + ko, bv3);
        CP_COMMIT();
    }

    float acc[4][8][4];
    #pragma unroll
    for (int mt = 0; mt < 4; mt++)
        #pragma unroll
        for (int nt = 0; nt < 8; nt++)
            #pragma unroll
            for (int i = 0; i < 4; i++) acc[mt][nt][i] = 0.f;

    for (int ch = 0; ch < nch; ch++) {
        if (ch < nch - 2)       { CP_WAIT(2); }
        else if (ch == nch - 2) { CP_WAIT(1); }
        else                    { CP_WAIT(0); }
        __syncthreads();
        if (ch + 3 < nch) {
            uint32_t so = (uint32_t)((ch + 3) % NSTAGE) * (STAGE_W * 4);
            size_t ko = (size_t)((ch + 3) << 5) * 2;
            cp16(sA0 + so, gA0 + ko, true);
            cp16(sA1 + so, gA1 + ko, true);
            cp16(sB0 + so, gB0 + ko, bv0);
            cp16(sB1 + so, gB1 + ko, bv1);
            cp16(sB2 + so, gB2 + ko, bv2);
            cp16(sB3 + so, gB3 + ko, bv3);
            CP_COMMIT();
        }
        const uint32_t* AsS = sm + (ch % NSTAGE) * STAGE_W;
        const uint32_t* BsS = AsS + AS_W;
        #pragma unroll
        for (int ks = 0; ks < 2; ks++) {        // two k16 halves of BK=32
            int kb = ks * 8 + c;
            uint32_t af[4][4];
            #pragma unroll
            for (int mt = 0; mt < 4; mt++) {
                int m = wm * 64 + mt * 16 + q;
                af[mt][0] = AsS[m * SSTRIDE + kb];
                af[mt][1] = AsS[(m + 8) * SSTRIDE + kb];
                af[mt][2] = AsS[m * SSTRIDE + kb + 4];
                af[mt][3] = AsS[(m + 8) * SSTRIDE + kb + 4];
            }
            uint32_t bf[8][2];
            #pragma unroll
            for (int nt = 0; nt < 8; nt++) {
                int n = wn * 64 + nt * 8 + q;
                bf[nt][0] = BsS[n * SSTRIDE + kb];
                bf[nt][1] = BsS[n * SSTRIDE + kb + 4];
            }
            #pragma unroll
            for (int mt = 0; mt < 4; mt++)
                #pragma unroll
                for (int nt = 0; nt < 8; nt++)
                    mma_bf16(acc[mt][nt], af[mt], bf[nt]);
        }
    }

    // epilogue: registers -> global as pairs
    #pragma unroll
    for (int mt = 0; mt < 4; mt++) {
        #pragma unroll
        for (int nt = 0; nt < 8; nt++) {
            int gr = brow + wm * 64 + mt * 16 + q;
            int gc = bcol + wn * 64 + nt * 8 + c * 2;
            if (gc < N) {
                #pragma unroll
                for (int half = 0; half < 2; half++) {
                    int row = gr + half * 8;
                    float v0 = acc[mt][nt][half * 2 + 0];
                    float v1 = acc[mt][nt][half * 2 + 1];
                    if (EPI == 1) {
                        v0 += bias[gc];     v1 += bias[gc + 1];
                        v0 = (v0 > 20.f) ? v0 : log1pf(expf(v0));
                        v1 = (v1 > 20.f) ? v1 : log1pf(expf(v1));
                    } else if (EPI == 2) {
                        float2 rz = *reinterpret_cast<const float2*>(
                            &resid[(size_t)row * ldc + gc]);
                        v0 += rz.x; v1 += rz.y;
                    }
                    store_pair(C, (size_t)row * ldc + gc, v0, v1);
                }
            }
        }
    }
}

// ---------------- RMSNorm: one block per token, bf16 output -----------------
__global__ __launch_bounds__(256) void rmsnorm_kernel(
    const float* __restrict__ x, bf16* __restrict__ u)
{
    size_t row = blockIdx.x;
    const float4* xr = reinterpret_cast<const float4*>(x + row * DMODEL);
    int tid = threadIdx.x;
    float4 v = xr[tid];
    float ss = v.x * v.x + v.y * v.y + v.z * v.z + v.w * v.w;
    #pragma unroll
    for (int o = 16; o > 0; o >>= 1) ss += __shfl_xor_sync(0xffffffffu, ss, o);
    __shared__ float ws[8];
    if ((tid & 31) == 0) ws[tid >> 5] = ss;
    __syncthreads();
    float tot = 0.f;
    #pragma unroll
    for (int w = 0; w < 8; w++) tot += ws[w];
    float sc = rsqrtf(tot * (1.f / DMODEL) + 1e-6f);
    bf162 lo = __floats2bfloat162_rn(v.x * sc, v.y * sc);
    bf162 hi = __floats2bfloat162_rn(v.z * sc, v.w * sc);
    uint2 o;
    o.x = *reinterpret_cast<uint32_t*>(&lo);
    o.y = *reinterpret_cast<uint32_t*>(&hi);
    *reinterpret_cast<uint2*>(u + row * DMODEL + (size_t)tid * 4) = o;
}

// ------- causal depthwise conv (width 4) + SiLU: 4 ch x 4 tokens/thread -----
__global__ __launch_bounds__(256) void conv_silu_kernel(
    const bf16* __restrict__ xz,       // [NTOK, 4096] bf16, xc = cols [0,2048)
    const float* __restrict__ cw,      // [2048, 4]
    const float* __restrict__ cb,
    bf16* __restrict__ xc)             // [NTOK, 2048] bf16
{
    int idx = blockIdx.x * 256 + threadIdx.x;   // NTOK/4 * DINNER/4 jobs
    int e4 = (idx & (DINNER / 4 - 1)) * 4;
    int rg = idx >> 9;
    int r0 = rg * 4;
    int t0 = r0 & (SEQ - 1);

    float4 w0 = *reinterpret_cast<const float4*>(cw + (size_t)(e4 + 0) * 4);
    float4 w1 = *reinterpret_cast<const float4*>(cw + (size_t)(e4 + 1) * 4);
    float4 w2 = *reinterpret_cast<const float4*>(cw + (size_t)(e4 + 2) * 4);
    float4 w3 = *reinterpret_cast<const float4*>(cw + (size_t)(e4 + 3) * 4);
    float4 bias = *reinterpret_cast<const float4*>(cb + e4);

    float4 xv[7];
    #pragma unroll
    for (int j = 0; j < 7; j++) {
        int dt_ = j - 3;
        if (t0 + dt_ >= 0) {
            uint2 raw = *reinterpret_cast<const uint2*>(
                xz + (size_t)(r0 + dt_) * (2 * DINNER) + e4);
            float2 f0 = __bfloat1622float2(*reinterpret_cast<bf162*>(&raw.x));
            float2 f1 = __bfloat1622float2(*reinterpret_cast<bf162*>(&raw.y));
            xv[j] = make_float4(f0.x, f0.y, f1.x, f1.y);
        } else {
            xv[j] = make_float4(0.f, 0.f, 0.f, 0.f);
        }
    }

    #pragma unroll
    for (int i = 0; i < 4; i++) {
        float4 acc = bias;
        #pragma unroll
        for (int k = 0; k < 4; k++) {
            float4 x4 = xv[i + k];
            acc.x = fmaf((&w0.x)[k], x4.x, acc.x);
            acc.y = fmaf((&w1.x)[k], x4.y, acc.y);
            acc.z = fmaf((&w2.x)[k], x4.z, acc.z);
            acc.w = fmaf((&w3.x)[k], x4.w, acc.w);
        }
        float4 s;
        s.x = acc.x / (1.f + __expf(-acc.x));
        s.y = acc.y / (1.f + __expf(-acc.y));
        s.z = acc.z / (1.f + __expf(-acc.z));
        s.w = acc.w / (1.f + __expf(-acc.w));
        bf162 lo = __floats2bfloat162_rn(s.x, s.y);
        bf162 hi = __floats2bfloat162_rn(s.z, s.w);
        uint2 o;
        o.x = *reinterpret_cast<uint32_t*>(&lo);
        o.y = *reinterpret_cast<uint32_t*>(&hi);
        *reinterpret_cast<uint2*>(xc + (size_t)(r0 + i) * DINNER + e4) = o;
    }
}

// ---------------- selective scan: 4 threads/channel, time-unrolled x8 -------
#define TUNROLL 8
__global__ __launch_bounds__(128) void scan_kernel(
    const float* __restrict__ dt,      // fp32
    const bf16*  __restrict__ xc,      // bf16
    const bf16*  __restrict__ dbl,     // bf16 [NTOK,96]
    const bf16*  __restrict__ xz,      // bf16 (z = cols [2048,4096))
    const float* __restrict__ A_log,
    const float* __restrict__ D_skip,
    bf16* __restrict__ y)              // bf16
{
    int idx = blockIdx.x * 128 + threadIdx.x;     // 0..32767
    int ch = idx >> 2, sub = idx & 3;
    int b = ch >> 11, e = ch & (DINNER - 1);

    float A0, A1, A2, A3;
    {
        const float* ap = A_log + (size_t)e * DSTATE + sub * 4;
        A0 = -expf(ap[0]); A1 = -expf(ap[1]);
        A2 = -expf(ap[2]); A3 = -expf(ap[3]);
    }
    float h0 = 0.f, h1 = 0.f, h2 = 0.f, h3 = 0.f;
    float Dv = D_skip[e];
    size_t base = (size_t)b * SEQ;

    const float* pdt = dt  + base * DINNER + e;
    const bf16*  pxc = xc  + base * DINNER + e;
    const bf16*  pz  = xz  + base * (2 * DINNER) + DINNER + e;
    const bf16*  pbc = dbl + base * DBL_W + DTRANK + sub * 4;
    bf16*        py  = y   + base * DINNER + e;

    for (int t = 0; t < SEQ; t += TUNROLL) {
        float dtv[TUNROLL], xv[TUNROLL], zv[TUNROLL];
        float2 B01[TUNROLL], B23[TUNROLL], C01[TUNROLL], C23[TUNROLL];
        #pragma unroll
        for (int j = 0; j < TUNROLL; j++) {
            dtv[j] = __ldcs(pdt + (size_t)j * DINNER);
            xv[j]  = __bfloat162float(pxc[(size_t)j * DINNER]);
            const bf162* pb = reinterpret_cast<const bf162*>(pbc + (size_t)j * DBL_W);
            B01[j] = __bfloat1622float2(pb[0]);
            B23[j] = __bfloat1622float2(pb[1]);
            const bf162* pc = reinterpret_cast<const bf162*>(
                pbc + (size_t)j * DBL_W + DSTATE);
            C01[j] = __bfloat1622float2(pc[0]);
            C23[j] = __bfloat1622float2(pc[1]);
        }
        if (sub == 0) {
            #pragma unroll
            for (int j = 0; j < TUNROLL; j++)
                zv[j] = __bfloat162float(pz[(size_t)j * 2 * DINNER]);
        }
        #pragma unroll
        for (int j = 0; j < TUNROLL; j++) {
            float dtx = dtv[j] * xv[j];
            h0 = fmaf(h0, __expf(dtv[j] * A0), dtx * B01[j].x);
            h1 = fmaf(h1, __expf(dtv[j] * A1), dtx * B01[j].y);
            h2 = fmaf(h2, __expf(dtv[j] * A2), dtx * B23[j].x);
            h3 = fmaf(h3, __expf(dtv[j] * A3), dtx * B23[j].y);
            float yv = h0 * C01[j].x;
            yv = fmaf(h1, C01[j].y, yv);
            yv = fmaf(h2, C23[j].x, yv);
            yv = fmaf(h3, C23[j].y, yv);
            yv += __shfl_xor_sync(0xffffffffu, yv, 1);
            yv += __shfl_xor_sync(0xffffffffu, yv, 2);
            if (sub == 0) {
                float g = __fdividef(zv[j], 1.f + __expf(-zv[j]));
                py[(size_t)j * DINNER] = __float2bfloat16((yv + Dv * xv[j]) * g);
            }
        }
        pdt += TUNROLL * DINNER; pxc += TUNROLL * DINNER;
        pz  += TUNROLL * 2 * DINNER;
        pbc += TUNROLL * DBL_W;  py += TUNROLL * DINNER;
    }
}

// ---------------- launch ----------------------------------------------------
extern "C" void kernel_launch(void* const* d_in, const int* in_sizes, int n_in,
                              void* d_out, int out_size)
{
    const float* x         = (const float*)d_in[0];
    const float* in_proj_w = (const float*)d_in[1];
    const float* conv_w    = (const float*)d_in[2];
    const float* conv_b    = (const float*)d_in[3];
    const float* x_proj_w  = (const float*)d_in[4];
    const float* dt_proj_w = (const float*)d_in[5];
    const float* dt_proj_b = (const float*)d_in[6];
    const float* A_log     = (const float*)d_in[7];
    const float* D_skip    = (const float*)d_in[8];
    const float* out_proj_w= (const float*)d_in[9];
    float* out = (float*)d_out;

    float *dtb;
    bf16 *xz, *u, *xc, *dbl, *yb, *w_in, *w_x, *w_dt, *w_out;
    cudaGetSymbolAddress((void**)&xz,   g_xz);
    cudaGetSymbolAddress((void**)&dtb,  g_dt);
    cudaGetSymbolAddress((void**)&u,    g_u);
    cudaGetSymbolAddress((void**)&xc,   g_xc);
    cudaGetSymbolAddress((void**)&dbl,  g_dbl);
    cudaGetSymbolAddress((void**)&yb,   g_y);
    cudaGetSymbolAddress((void**)&w_in, g_w_in);
    cudaGetSymbolAddress((void**)&w_x,  g_w_x);
    cudaGetSymbolAddress((void**)&w_dt, g_w_dt);
    cudaGetSymbolAddress((void**)&w_out,g_w_out);

    cudaFuncSetAttribute((const void*)mma_gemm_kernel<0, bf16>,
        cudaFuncAttributeMaxDynamicSharedMemorySize, GEMM_SMEM_BYTES);
    cudaFuncSetAttribute((const void*)mma_gemm_kernel<1, float>,
        cudaFuncAttributeMaxDynamicSharedMemorySize, GEMM_SMEM_BYTES);
    cudaFuncSetAttribute((const void*)mma_gemm_kernel<2, float>,
        cudaFuncAttributeMaxDynamicSharedMemorySize, GEMM_SMEM_BYTES);

    // 0) weights -> bf16, one kernel
    {
        int total4 = (int)((W_IN_SZ + W_X_SZ + W_DT_SZ + W_OUT_SZ) / 4);
        cvt_weights_kernel<<<(total4 + 255) / 256, 256>>>(
            (const float4*)in_proj_w, w_in,
            (const float4*)x_proj_w,  w_x,
            (const float4*)dt_proj_w, w_dt,
            (const float4*)out_proj_w,w_out);
    }

    // 1) RMSNorm -> u (bf16)
    rmsnorm_kernel<<<NTOK, 256>>>(x, u);

    // 2) in_proj: [16384,1024]bf16 @ [4096,1024]^T -> xz bf16
    mma_gemm_kernel<0, bf16><<<dim3((2 * DINNER) / 256, NTOK / 128), 256, GEMM_SMEM_BYTES>>>(
        u, DMODEL, w_in, DMODEL, xz, 2 * DINNER,
        2 * DINNER, DMODEL, nullptr, nullptr);

    // 3) causal depthwise conv + SiLU -> xc (bf16)
    conv_silu_kernel<<<(NTOK / 4) * (DINNER / 4) / 256, 256>>>(xz, conv_w, conv_b, xc);

    // 4) x_proj: [16384,2048]bf16 @ [96,2048]^T -> dbl (bf16)
    mma_gemm_kernel<0, bf16><<<dim3(1, NTOK / 128), 256, GEMM_SMEM_BYTES>>>(
        xc, DINNER, w_x, DINNER, dbl, DBL_W,
        DBL_W, DINNER, nullptr, nullptr);

    // 5) dt_proj + bias + softplus: [16384,64]bf16 @ [2048,64]^T -> dt fp32
    mma_gemm_kernel<1, float><<<dim3(DINNER / 256, NTOK / 128), 256, GEMM_SMEM_BYTES>>>(
        dbl, DBL_W, w_dt, DTRANK, dtb, DINNER,
        DINNER, DTRANK, dt_proj_b, nullptr);

    // 6) selective scan + D skip + SiLU(z) gating -> y (bf16)
    scan_kernel<<<(BATCH * DINNER * 4) / 128, 128>>>(dtb, xc, dbl, xz, A_log, D_skip, yb);

    // 7) out_proj + residual: [16384,2048]bf16 @ [1024,2048]^T + x -> out fp32
    mma_gemm_kernel<2, float><<<dim3(DMODEL / 256, NTOK / 128), 256, GEMM_SMEM_BYTES>>>(
        yb, DINNER, w_out, DINNER, out, DMODEL,
        DMODEL, DINNER, nullptr, x);
}

// round 16
// speedup vs baseline: 1.7576x; 1.7576x over previous
#include <cuda_runtime.h>
#include <cuda_bf16.h>
#include <math.h>
#include <stdint.h>

#define BATCH   4
#define SEQ     4096
#define DMODEL  1024
#define DINNER  2048
#define DSTATE  16
#define DTRANK  64
#define NTOK    (BATCH * SEQ)          // 16384
#define DBL_W   (DTRANK + 2 * DSTATE)  // 96

typedef __nv_bfloat16 bf16;
typedef __nv_bfloat162 bf162;

// ---------------- scratch (static device globals: allocation-free) ----------
__device__ float g_xz [(size_t)NTOK * 2 * DINNER];   // fp32: conv input + z gate
__device__ float g_dt [(size_t)NTOK * DINNER];       // fp32: exp-sensitive
__device__ bf16  g_u  [(size_t)NTOK * DMODEL];       // MMA operands: bf16
__device__ bf16  g_xc [(size_t)NTOK * DINNER];
__device__ bf16  g_dbl[(size_t)NTOK * DBL_W];
__device__ bf16  g_y  [(size_t)NTOK * DINNER];
#define W_IN_SZ  ((size_t)(2 * DINNER) * DMODEL)
#define W_X_SZ   ((size_t)DBL_W * DINNER)
#define W_DT_SZ  ((size_t)DINNER * DTRANK)
#define W_OUT_SZ ((size_t)DMODEL * DINNER)
__device__ bf16 g_w_in [W_IN_SZ];
__device__ bf16 g_w_x  [W_X_SZ];
__device__ bf16 g_w_dt [W_DT_SZ];
__device__ bf16 g_w_out[W_OUT_SZ];

// ---------------- helpers ----------------------------------------------------
__device__ __forceinline__ uint32_t cvta_smem_u32(const void* p) {
    uint32_t a;
    asm("{ .reg .u64 t; cvta.to.shared.u64 t, %1; cvt.u32.u64 %0, t; }"
        : "=r"(a) : "l"(p));
    return a;
}
__device__ __forceinline__ void cp16(uint32_t sdst, const void* gsrc, bool valid) {
    int sz = valid ? 16 : 0;
    asm volatile("cp.async.cg.shared.global [%0], [%1], 16, %2;"
                 :: "r"(sdst), "l"(gsrc), "r"(sz) : "memory");
}
#define CP_COMMIT() asm volatile("cp.async.commit_group;" ::: "memory")
#define CP_WAIT(n)  asm volatile("cp.async.wait_group %0;" :: "n"(n) : "memory")

__device__ __forceinline__ void mma_bf16(float* d, const uint32_t* a,
                                         const uint32_t* b) {
    asm volatile(
        "mma.sync.aligned.m16n8k16.row.col.f32.bf16.bf16.f32 "
        "{%0,%1,%2,%3}, {%4,%5,%6,%7}, {%8,%9}, {%0,%1,%2,%3};"
        : "+f"(d[0]), "+f"(d[1]), "+f"(d[2]), "+f"(d[3])
        : "r"(a[0]), "r"(a[1]), "r"(a[2]), "r"(a[3]), "r"(b[0]), "r"(b[1]));
}

__device__ __forceinline__ void store_pair(float* C, size_t off, float v0, float v1) {
    float2 o; o.x = v0; o.y = v1;
    *reinterpret_cast<float2*>(C + off) = o;
}
__device__ __forceinline__ void store_pair(bf16* C, size_t off, float v0, float v1) {
    *reinterpret_cast<bf162*>(C + off) = __floats2bfloat162_rn(v0, v1);
}

// ---------------- weight f32 -> bf16 pre-pass (all 4, 1 kernel) -------------
__global__ __launch_bounds__(256) void cvt_weights_kernel(
    const float4* __restrict__ w_in_s,  bf16* __restrict__ w_in_d,
    const float4* __restrict__ w_x_s,   bf16* __restrict__ w_x_d,
    const float4* __restrict__ w_dt_s,  bf16* __restrict__ w_dt_d,
    const float4* __restrict__ w_out_s, bf16* __restrict__ w_out_d)
{
    const int n0 = W_IN_SZ / 4, n1 = n0 + W_X_SZ / 4;
    const int n2 = n1 + W_DT_SZ / 4, n3 = n2 + W_OUT_SZ / 4;
    int i = blockIdx.x * 256 + threadIdx.x;
    const float4* src; bf16* dst; int off;
    if      (i < n0) { src = w_in_s;  dst = w_in_d;  off = i; }
    else if (i < n1) { src = w_x_s;   dst = w_x_d;   off = i - n0; }
    else if (i < n2) { src = w_dt_s;  dst = w_dt_d;  off = i - n1; }
    else if (i < n3) { src = w_out_s; dst = w_out_d; off = i - n2; }
    else return;
    float4 v = src[off];
    bf162 lo = __floats2bfloat162_rn(v.x, v.y);
    bf162 hi = __floats2bfloat162_rn(v.z, v.w);
    uint2 o;
    o.x = *reinterpret_cast<uint32_t*>(&lo);
    o.y = *reinterpret_cast<uint32_t*>(&hi);
    *reinterpret_cast<uint2*>(dst + (size_t)off * 4) = o;
}

// ================ bf16 mma.sync GEMM: C = A[M,K] @ W[N,K]^T =================
// CTA 128x256, 256 threads (8 warps 2x4), warp tile 64x64 (4x8 m16n8k16).
// BK=32 bf16 per stage, 4-stage cp.async, scalar-LDS fragment loads, 1 CTA/SM.
// EPI: 0 none, 1 softplus(acc+bias[n]), 2 acc+resid. OutT: float or bf16.

#define SSTRIDE 20               // 4B words per 32-bf16 row (16 data + 4 pad)
#define AS_W    (128 * SSTRIDE)
#define BS_W    (256 * SSTRIDE)
#define STAGE_W (AS_W + BS_W)    // 7680 words = 30720 B
#define NSTAGE  4
#define GEMM_SMEM_BYTES (NSTAGE * STAGE_W * 4)   // 122880

template <int EPI, typename OutT>
__global__ __launch_bounds__(256, 1) void mma_gemm_kernel(
    const bf16* __restrict__ A, int lda,
    const bf16* __restrict__ W, int ldb,
    OutT* __restrict__ C, int ldc,
    int N, int K,
    const float* __restrict__ bias,
    const float* __restrict__ resid)
{
    extern __shared__ uint32_t sm[];
    uint32_t smb = cvta_smem_u32(sm);

    int tid = threadIdx.x;
    int lane = tid & 31;
    int q = lane >> 2, c = lane & 3;
    int wid = tid >> 5;
    int wm = wid >> 2, wn = wid & 3;            // 2 x 4 warp grid
    int brow = blockIdx.y * 128, bcol = blockIdx.x * 256;

    // cp.async mapping: rows tid>>2 (+64k), 16B piece tid&3; row = 64B of bf16
    int rA = tid >> 2;                          // 0..63
    int pq = (tid & 3) * 16;                    // byte piece within row
    const char* gA0 = (const char*)(A + (size_t)(brow + rA) * lda) + pq;
    const char* gA1 = (const char*)(A + (size_t)(brow + rA + 64) * lda) + pq;
    bool bv0 = (bcol + rA)       < N;
    bool bv1 = (bcol + rA + 64)  < N;
    bool bv2 = (bcol + rA + 128) < N;
    bool bv3 = (bcol + rA + 192) < N;
    const char* gB0 = (const char*)(W + (size_t)(bv0 ? bcol + rA       : 0) * ldb) + pq;
    const char* gB1 = (const char*)(W + (size_t)(bv1 ? bcol + rA + 64  : 0) * ldb) + pq;
    const char* gB2 = (const char*)(W + (size_t)(bv2 ? bcol + rA + 128 : 0) * ldb) + pq;
    const char* gB3 = (const char*)(W + (size_t)(bv3 ? bcol + rA + 192 : 0) * ldb) + pq;

    uint32_t sA0 = smb + (uint32_t)(rA * SSTRIDE) * 4 + pq;
    uint32_t sA1 = sA0 + 64 * SSTRIDE * 4;
    uint32_t sB0 = smb + (uint32_t)(AS_W + rA * SSTRIDE) * 4 + pq;
    uint32_t sB1 = sB0 + 64  * SSTRIDE * 4;
    uint32_t sB2 = sB0 + 128 * SSTRIDE * 4;
    uint32_t sB3 = sB0 + 192 * SSTRIDE * 4;

    int nch = K >> 5;                  // BK = 32 bf16 (64 bytes per row)
    int npro = nch < 3 ? nch : 3;

    for (int p = 0; p < npro; p++) {
        uint32_t so = (uint32_t)p * (STAGE_W * 4);
        size_t ko = (size_t)(p << 5) * 2;       // 32 bf16 = 64 bytes
        cp16(sA0 + so, gA0 + ko, true);
        cp16(sA1 + so, gA1 + ko, true);
        cp16(sB0 + so, gB0 + ko, bv0);
        cp16(sB1 + so, gB1 + ko, bv1);
        cp16(sB2 + so, gB2 + ko, bv2);
        cp16(sB3 + so, gB3 + ko, bv3);
        CP_COMMIT();
    }

    float acc[4][8][4];
    #pragma unroll
    for (int mt = 0; mt < 4; mt++)
        #pragma unroll
        for (int nt = 0; nt < 8; nt++)
            #pragma unroll
            for (int i = 0; i < 4; i++) acc[mt][nt][i] = 0.f;

    for (int ch = 0; ch < nch; ch++) {
        if (ch < nch - 2)       { CP_WAIT(2); }
        else if (ch == nch - 2) { CP_WAIT(1); }
        else                    { CP_WAIT(0); }
        __syncthreads();
        if (ch + 3 < nch) {
            uint32_t so = (uint32_t)((ch + 3) % NSTAGE) * (STAGE_W * 4);
            size_t ko = (size_t)((ch + 3) << 5) * 2;
            cp16(sA0 + so, gA0 + ko, true);
            cp16(sA1 + so, gA1 + ko, true);
            cp16(sB0 + so, gB0 + ko, bv0);
            cp16(sB1 + so, gB1 + ko, bv1);
            cp16(sB2 + so, gB2 + ko, bv2);
            cp16(sB3 + so, gB3 + ko, bv3);
            CP_COMMIT();
        }
        const uint32_t* AsS = sm + (ch % NSTAGE) * STAGE_W;
        const uint32_t* BsS = AsS + AS_W;
        #pragma unroll
        for (int ks = 0; ks < 2; ks++) {        // two k16 halves of BK=32
            int kb = ks * 8 + c;
            uint32_t af[4][4];
            #pragma unroll
            for (int mt = 0; mt < 4; mt++) {
                int m = wm * 64 + mt * 16 + q;
                af[mt][0] = AsS[m * SSTRIDE + kb];
                af[mt][1] = AsS[(m + 8) * SSTRIDE + kb];
                af[mt][2] = AsS[m * SSTRIDE + kb + 4];
                af[mt][3] = AsS[(m + 8) * SSTRIDE + kb + 4];
            }
            uint32_t bf[8][2];
            #pragma unroll
            for (int nt = 0; nt < 8; nt++) {
                int n = wn * 64 + nt * 8 + q;
                bf[nt][0] = BsS[n * SSTRIDE + kb];
                bf[nt][1] = BsS[n * SSTRIDE + kb + 4];
            }
            #pragma unroll
            for (int mt = 0; mt < 4; mt++)
                #pragma unroll
                for (int nt = 0; nt < 8; nt++)
                    mma_bf16(acc[mt][nt], af[mt], bf[nt]);
        }
    }

    // epilogue: registers -> global as pairs
    #pragma unroll
    for (int mt = 0; mt < 4; mt++) {
        #pragma unroll
        for (int nt = 0; nt < 8; nt++) {
            int gr = brow + wm * 64 + mt * 16 + q;
            int gc = bcol + wn * 64 + nt * 8 + c * 2;
            if (gc < N) {
                #pragma unroll
                for (int half = 0; half < 2; half++) {
                    int row = gr + half * 8;
                    float v0 = acc[mt][nt][half * 2 + 0];
                    float v1 = acc[mt][nt][half * 2 + 1];
                    if (EPI == 1) {
                        v0 += bias[gc];     v1 += bias[gc + 1];
                        v0 = (v0 > 20.f) ? v0 : log1pf(expf(v0));
                        v1 = (v1 > 20.f) ? v1 : log1pf(expf(v1));
                    } else if (EPI == 2) {
                        float2 rz = *reinterpret_cast<const float2*>(
                            &resid[(size_t)row * ldc + gc]);
                        v0 += rz.x; v1 += rz.y;
                    }
                    store_pair(C, (size_t)row * ldc + gc, v0, v1);
                }
            }
        }
    }
}

// ---------------- RMSNorm: one block per token, bf16 output -----------------
__global__ __launch_bounds__(256) void rmsnorm_kernel(
    const float* __restrict__ x, bf16* __restrict__ u)
{
    size_t row = blockIdx.x;
    const float4* xr = reinterpret_cast<const float4*>(x + row * DMODEL);
    int tid = threadIdx.x;
    float4 v = xr[tid];
    float ss = v.x * v.x + v.y * v.y + v.z * v.z + v.w * v.w;
    #pragma unroll
    for (int o = 16; o > 0; o >>= 1) ss += __shfl_xor_sync(0xffffffffu, ss, o);
    __shared__ float ws[8];
    if ((tid & 31) == 0) ws[tid >> 5] = ss;
    __syncthreads();
    float tot = 0.f;
    #pragma unroll
    for (int w = 0; w < 8; w++) tot += ws[w];
    float sc = rsqrtf(tot * (1.f / DMODEL) + 1e-6f);
    bf162 lo = __floats2bfloat162_rn(v.x * sc, v.y * sc);
    bf162 hi = __floats2bfloat162_rn(v.z * sc, v.w * sc);
    uint2 o;
    o.x = *reinterpret_cast<uint32_t*>(&lo);
    o.y = *reinterpret_cast<uint32_t*>(&hi);
    *reinterpret_cast<uint2*>(u + row * DMODEL + (size_t)tid * 4) = o;
}

// ------- causal depthwise conv (width 4) + SiLU: 4 ch x 4 tokens/thread -----
__global__ __launch_bounds__(256) void conv_silu_kernel(
    const float* __restrict__ xz,      // [NTOK, 4096] fp32, xc = cols [0,2048)
    const float* __restrict__ cw,      // [2048, 4]
    const float* __restrict__ cb,
    bf16* __restrict__ xc)             // [NTOK, 2048] bf16
{
    int idx = blockIdx.x * 256 + threadIdx.x;   // NTOK/4 * DINNER/4 jobs
    int e4 = (idx & (DINNER / 4 - 1)) * 4;
    int rg = idx >> 9;
    int r0 = rg * 4;
    int t0 = r0 & (SEQ - 1);

    float4 w0 = *reinterpret_cast<const float4*>(cw + (size_t)(e4 + 0) * 4);
    float4 w1 = *reinterpret_cast<const float4*>(cw + (size_t)(e4 + 1) * 4);
    float4 w2 = *reinterpret_cast<const float4*>(cw + (size_t)(e4 + 2) * 4);
    float4 w3 = *reinterpret_cast<const float4*>(cw + (size_t)(e4 + 3) * 4);
    float4 bias = *reinterpret_cast<const float4*>(cb + e4);

    float4 xv[7];
    #pragma unroll
    for (int j = 0; j < 7; j++) {
        int dt_ = j - 3;
        if (t0 + dt_ >= 0)
            xv[j] = __ldcs(reinterpret_cast<const float4*>(
                xz + (size_t)(r0 + dt_) * (2 * DINNER) + e4));
        else
            xv[j] = make_float4(0.f, 0.f, 0.f, 0.f);
    }

    #pragma unroll
    for (int i = 0; i < 4; i++) {
        float4 acc = bias;
        #pragma unroll
        for (int k = 0; k < 4; k++) {
            float4 x4 = xv[i + k];
            acc.x = fmaf((&w0.x)[k], x4.x, acc.x);
            acc.y = fmaf((&w1.x)[k], x4.y, acc.y);
            acc.z = fmaf((&w2.x)[k], x4.z, acc.z);
            acc.w = fmaf((&w3.x)[k], x4.w, acc.w);
        }
        float4 s;
        s.x = acc.x / (1.f + __expf(-acc.x));
        s.y = acc.y / (1.f + __expf(-acc.y));
        s.z = acc.z / (1.f + __expf(-acc.z));
        s.w = acc.w / (1.f + __expf(-acc.w));
        bf162 lo = __floats2bfloat162_rn(s.x, s.y);
        bf162 hi = __floats2bfloat162_rn(s.z, s.w);
        uint2 o;
        o.x = *reinterpret_cast<uint32_t*>(&lo);
        o.y = *reinterpret_cast<uint32_t*>(&hi);
        *reinterpret_cast<uint2*>(xc + (size_t)(r0 + i) * DINNER + e4) = o;
    }
}

// ---------------- selective scan: 4 threads/channel, time-unrolled x8 -------
#define TUNROLL 8
__global__ __launch_bounds__(128) void scan_kernel(
    const float* __restrict__ dt,      // fp32
    const bf16*  __restrict__ xc,      // bf16
    const bf16*  __restrict__ dbl,     // bf16 [NTOK,96]
    const float* __restrict__ xz,      // fp32 (z = cols [2048,4096))
    const float* __restrict__ A_log,
    const float* __restrict__ D_skip,
    bf16* __restrict__ y)              // bf16
{
    int idx = blockIdx.x * 128 + threadIdx.x;     // 0..32767
    int ch = idx >> 2, sub = idx & 3;
    int b = ch >> 11, e = ch & (DINNER - 1);

    float A0, A1, A2, A3;
    {
        const float* ap = A_log + (size_t)e * DSTATE + sub * 4;
        A0 = -expf(ap[0]); A1 = -expf(ap[1]);
        A2 = -expf(ap[2]); A3 = -expf(ap[3]);
    }
    float h0 = 0.f, h1 = 0.f, h2 = 0.f, h3 = 0.f;
    float Dv = D_skip[e];
    size_t base = (size_t)b * SEQ;

    const float* pdt = dt  + base * DINNER + e;
    const bf16*  pxc = xc  + base * DINNER + e;
    const float* pz  = xz  + base * (2 * DINNER) + DINNER + e;
    const bf16*  pbc = dbl + base * DBL_W + DTRANK + sub * 4;
    bf16*        py  = y   + base * DINNER + e;

    for (int t = 0; t < SEQ; t += TUNROLL) {
        float dtv[TUNROLL], xv[TUNROLL], zv[TUNROLL];
        float2 B01[TUNROLL], B23[TUNROLL], C01[TUNROLL], C23[TUNROLL];
        #pragma unroll
        for (int j = 0; j < TUNROLL; j++) {
            dtv[j] = __ldcs(pdt + (size_t)j * DINNER);
            xv[j]  = __bfloat162float(pxc[(size_t)j * DINNER]);
            const bf162* pb = reinterpret_cast<const bf162*>(pbc + (size_t)j * DBL_W);
            B01[j] = __bfloat1622float2(pb[0]);
            B23[j] = __bfloat1622float2(pb[1]);
            const bf162* pc = reinterpret_cast<const bf162*>(
                pbc + (size_t)j * DBL_W + DSTATE);
            C01[j] = __bfloat1622float2(pc[0]);
            C23[j] = __bfloat1622float2(pc[1]);
        }
        if (sub == 0) {
            #pragma unroll
            for (int j = 0; j < TUNROLL; j++)
                zv[j] = __ldcs(pz + (size_t)j * 2 * DINNER);
        }
        #pragma unroll
        for (int j = 0; j < TUNROLL; j++) {
            float dtx = dtv[j] * xv[j];
            h0 = fmaf(h0, __expf(dtv[j] * A0), dtx * B01[j].x);
            h1 = fmaf(h1, __expf(dtv[j] * A1), dtx * B01[j].y);
            h2 = fmaf(h2, __expf(dtv[j] * A2), dtx * B23[j].x);
            h3 = fmaf(h3, __expf(dtv[j] * A3), dtx * B23[j].y);
            float yv = h0 * C01[j].x;
            yv = fmaf(h1, C01[j].y, yv);
            yv = fmaf(h2, C23[j].x, yv);
            yv = fmaf(h3, C23[j].y, yv);
            yv += __shfl_xor_sync(0xffffffffu, yv, 1);
            yv += __shfl_xor_sync(0xffffffffu, yv, 2);
            if (sub == 0) {
                float g = __fdividef(zv[j], 1.f + __expf(-zv[j]));
                py[(size_t)j * DINNER] = __float2bfloat16((yv + Dv * xv[j]) * g);
            }
        }
        pdt += TUNROLL * DINNER; pxc += TUNROLL * DINNER;
        pz  += TUNROLL * 2 * DINNER;
        pbc += TUNROLL * DBL_W;  py += TUNROLL * DINNER;
    }
}

// ---------------- launch ----------------------------------------------------
extern "C" void kernel_launch(void* const* d_in, const int* in_sizes, int n_in,
                              void* d_out, int out_size)
{
    const float* x         = (const float*)d_in[0];
    const float* in_proj_w = (const float*)d_in[1];
    const float* conv_w    = (const float*)d_in[2];
    const float* conv_b    = (const float*)d_in[3];
    const float* x_proj_w  = (const float*)d_in[4];
    const float* dt_proj_w = (const float*)d_in[5];
    const float* dt_proj_b = (const float*)d_in[6];
    const float* A_log     = (const float*)d_in[7];
    const float* D_skip    = (const float*)d_in[8];
    const float* out_proj_w= (const float*)d_in[9];
    float* out = (float*)d_out;

    float *xz, *dtb;
    bf16 *u, *xc, *dbl, *yb, *w_in, *w_x, *w_dt, *w_out;
    cudaGetSymbolAddress((void**)&xz,   g_xz);
    cudaGetSymbolAddress((void**)&dtb,  g_dt);
    cudaGetSymbolAddress((void**)&u,    g_u);
    cudaGetSymbolAddress((void**)&xc,   g_xc);
    cudaGetSymbolAddress((void**)&dbl,  g_dbl);
    cudaGetSymbolAddress((void**)&yb,   g_y);
    cudaGetSymbolAddress((void**)&w_in, g_w_in);
    cudaGetSymbolAddress((void**)&w_x,  g_w_x);
    cudaGetSymbolAddress((void**)&w_dt, g_w_dt);
    cudaGetSymbolAddress((void**)&w_out,g_w_out);

    cudaFuncSetAttribute((const void*)mma_gemm_kernel<0, float>,
        cudaFuncAttributeMaxDynamicSharedMemorySize, GEMM_SMEM_BYTES);
    cudaFuncSetAttribute((const void*)mma_gemm_kernel<0, bf16>,
        cudaFuncAttributeMaxDynamicSharedMemorySize, GEMM_SMEM_BYTES);
    cudaFuncSetAttribute((const void*)mma_gemm_kernel<1, float>,
        cudaFuncAttributeMaxDynamicSharedMemorySize, GEMM_SMEM_BYTES);
    cudaFuncSetAttribute((const void*)mma_gemm_kernel<2, float>,
        cudaFuncAttributeMaxDynamicSharedMemorySize, GEMM_SMEM_BYTES);

    // 0) weights -> bf16, one kernel
    {
        int total4 = (int)((W_IN_SZ + W_X_SZ + W_DT_SZ + W_OUT_SZ) / 4);
        cvt_weights_kernel<<<(total4 + 255) / 256, 256>>>(
            (const float4*)in_proj_w, w_in,
            (const float4*)x_proj_w,  w_x,
            (const float4*)dt_proj_w, w_dt,
            (const float4*)out_proj_w,w_out);
    }

    // 1) RMSNorm -> u (bf16)
    rmsnorm_kernel<<<NTOK, 256>>>(x, u);

    // 2) in_proj: [16384,1024]bf16 @ [4096,1024]^T -> xz fp32
    mma_gemm_kernel<0, float><<<dim3((2 * DINNER) / 256, NTOK / 128), 256, GEMM_SMEM_BYTES>>>(
        u, DMODEL, w_in, DMODEL, xz, 2 * DINNER,
        2 * DINNER, DMODEL, nullptr, nullptr);

    // 3) causal depthwise conv + SiLU -> xc (bf16)
    conv_silu_kernel<<<(NTOK / 4) * (DINNER / 4) / 256, 256>>>(xz, conv_w, conv_b, xc);

    // 4) x_proj: [16384,2048]bf16 @ [96,2048]^T -> dbl (bf16)
    mma_gemm_kernel<0, bf16><<<dim3(1, NTOK / 128), 256, GEMM_SMEM_BYTES>>>(
        xc, DINNER, w_x, DINNER, dbl, DBL_W,
        DBL_W, DINNER, nullptr, nullptr);

    // 5) dt_proj + bias + softplus: [16384,64]bf16 @ [2048,64]^T -> dt fp32
    mma_gemm_kernel<1, float><<<dim3(DINNER / 256, NTOK / 128), 256, GEMM_SMEM_BYTES>>>(
        dbl, DBL_W, w_dt, DTRANK, dtb, DINNER,
        DINNER, DTRANK, dt_proj_b, nullptr);

    // 6) selective scan + D skip + SiLU(z) gating -> y (bf16)
    scan_kernel<<<(BATCH * DINNER * 4) / 128, 128>>>(dtb, xc, dbl, xz, A_log, D_skip, yb);

    // 7) out_proj + residual: [16384,2048]bf16 @ [1024,2048]^T + x -> out fp32
    mma_gemm_kernel<2, float><<<dim3(DMODEL / 256, NTOK / 128), 256, GEMM_SMEM_BYTES>>>(
        yb, DINNER, w_out, DINNER, out, DMODEL,
        DMODEL, DINNER, nullptr, x);
}